// round 7
// baseline (speedup 1.0000x reference)
#include <cuda_runtime.h>

// GraphMultiHeadAttention: B=8, N=1024, D=256, H=4, HO=64, T=5
// K1: h = x @ W, ho-pair blocked f32x2
// K1b: e_src/e_dst score tables
// K2: masked edge-typed attention; p stored pre-splatted (p,p) in smem so the
//     AV mainloop is pure {LDS.v2.u64, LDG.128, FFMA2} — no packs.

#define BB 8
#define NN 1024
#define DD 256
#define HH 4
#define HOO 64
#define TT 5
#define RR 32
#define JC 32
#define NCH (NN / JC)

// k_attn smem layout (u64 units for ps)
#define PS_HS (RR * JC + 2)          // 1026 u64 per head (pad kills h-bank alias)
#define PS_BUF (HH * PS_HS)          // 4104
#define K2_SMEM_BYTES (2 * PS_BUF * 8 + 2 * 640 * 4 + 640 * 4 + 128 * 4)

typedef unsigned long long u64;

__device__ float g_h[BB * HH * NN * HOO];      // [B,H,N,HO]
__device__ float g_es[BB * HH * TT * NN];      // [B,H,T,N]
__device__ float g_ed[BB * HH * TT * NN];      // [B,H,T,N]

__device__ __forceinline__ u64 pack2(float lo, float hi) {
    u64 r; asm("mov.b64 %0, {%1, %2};" : "=l"(r) : "f"(lo), "f"(hi)); return r;
}
__device__ __forceinline__ void fma2(u64& acc, u64 a, u64 b) {
    asm("fma.rn.f32x2 %0, %1, %2, %0;" : "+l"(acc) : "l"(a), "l"(b));
}
__device__ __forceinline__ float2 unpack2(u64 v) {
    float2 f; asm("mov.b64 {%0, %1}, %2;" : "=f"(f.x), "=f"(f.y) : "l"(v)); return f;
}

// ---------------------------------------------------------------------------
// K1: projection. Grid 256 CTAs x 256 threads. CTA = 32 nodes, all 256 outputs.
// Thread = (h, ho-pair, 16 nodes). Per d: 1 LDG.64 (w), 2 packs, 8 LDS.64 (x
// node-pairs, broadcast), 16 FFMA2.
// ---------------------------------------------------------------------------
__global__ __launch_bounds__(256) void k_project(const float* __restrict__ x,
                                                 const float* __restrict__ W) {
    __shared__ float xs[DD][34];
    const int b = blockIdx.x >> 5;
    const int n0 = (blockIdx.x & 31) * 32;
    const int tid = threadIdx.x;

    {
        const float* xp = x + (b * NN + n0) * DD + tid;
#pragma unroll
        for (int nt = 0; nt < 32; nt++) xs[tid][nt] = xp[nt * DD];
    }
    __syncthreads();

    const int nh = tid >> 7;           // node half: 16 nodes
    const int h = (tid >> 5) & 3;
    const int hop = tid & 31;          // ho pair
    const int ho0 = hop * 2;
    const int nb = nh * 16;

    u64 acc[8][2];                     // [node-pair][ho of pair]
#pragma unroll
    for (int i = 0; i < 8; i++) acc[i][0] = acc[i][1] = 0ull;

    const float* wp = W + h * DD * HOO + ho0;
#pragma unroll 4
    for (int d = 0; d < DD; d++) {
        const float2 wv = __ldg(reinterpret_cast<const float2*>(wp + d * HOO));
        const u64 ws0 = pack2(wv.x, wv.x);
        const u64 ws1 = pack2(wv.y, wv.y);
#pragma unroll
        for (int i = 0; i < 8; i++) {
            const u64 xv = *reinterpret_cast<const u64*>(&xs[d][nb + 2 * i]);
            fma2(acc[i][0], xv, ws0);
            fma2(acc[i][1], xv, ws1);
        }
    }

    float* hp = g_h + ((b * HH + h) * NN + n0 + nb) * HOO + ho0;
#pragma unroll
    for (int i = 0; i < 8; i++) {
        const float2 f0 = unpack2(acc[i][0]);   // (n=2i, n=2i+1) @ ho0
        const float2 f1 = unpack2(acc[i][1]);   // @ ho0+1
        *reinterpret_cast<float2*>(hp + (2 * i + 0) * HOO) = make_float2(f0.x, f1.x);
        *reinterpret_cast<float2*>(hp + (2 * i + 1) * HOO) = make_float2(f0.y, f1.y);
    }
}

// ---------------------------------------------------------------------------
// K1b: score tables. Grid 1024 x 256; warp = one node.
// ---------------------------------------------------------------------------
__global__ __launch_bounds__(256) void k_scores(const float* __restrict__ a_src,
                                                const float* __restrict__ a_dst) {
    const int warp = threadIdx.x >> 5, lane = threadIdx.x & 31;
    const int node = blockIdx.x * 8 + warp;
    const int b = node >> 10;
    const int n = node & (NN - 1);

    float hv[2 * HH];
#pragma unroll
    for (int h = 0; h < HH; h++) {
        const float* hp = g_h + ((b * HH + h) * NN + n) * HOO;
        hv[h * 2 + 0] = hp[lane];
        hv[h * 2 + 1] = hp[32 + lane];
    }

#pragma unroll
    for (int h = 0; h < HH; h++) {
#pragma unroll
        for (int t = 0; t < TT; t++) {
            const int wi = (h * TT + t) * HOO;
            float ps = hv[h * 2] * a_src[wi + lane] + hv[h * 2 + 1] * a_src[wi + 32 + lane];
            float pd = hv[h * 2] * a_dst[wi + lane] + hv[h * 2 + 1] * a_dst[wi + 32 + lane];
#pragma unroll
            for (int off = 16; off; off >>= 1) {
                ps += __shfl_xor_sync(0xffffffffu, ps, off);
                pd += __shfl_xor_sync(0xffffffffu, pd, off);
            }
            if (lane == 0) {
                g_es[(b * HH + h) * TT * NN + t * NN + n] = ps;
                g_ed[(b * HH + h) * TT * NN + t * NN + n] = pd;
            }
        }
    }
}

// ---------------------------------------------------------------------------
// K2: attention + epilogue. Grid (32, 8), 256 threads, 2 CTAs/SM.
// Phase A: warp = 4 rows, lane = j. p = exp(lrelu(es+ed)) masked; stored as
//          splatted u64 (p,p).  Phase B: thread = (rq, h, hoq): 8 rows x 4 ho;
//          per (ri, jg): 2 LDS.v2.u64 + 8 FFMA2, v via ulonglong2 LDG.128.
// ---------------------------------------------------------------------------
__global__ __launch_bounds__(256, 2) void k_attn(const int* __restrict__ adj,
                                                 const float* __restrict__ bias,
                                                 const float* __restrict__ gamma,
                                                 const float* __restrict__ beta,
                                                 float* __restrict__ out) {
    extern __shared__ unsigned char smem_raw[];
    u64* ps = reinterpret_cast<u64*>(smem_raw);                 // [2][HH][PS_HS]
    float* ed = reinterpret_cast<float*>(ps + 2 * PS_BUF);      // [2][640]
    float* es = ed + 2 * 640;                                   // [32*4*5]
    float* sums = es + 640;                                     // [32*4]

    const int b = blockIdx.y;
    const int i0 = blockIdx.x * RR;
    const int tid = threadIdx.x;
    const int w = tid >> 5, lane = tid & 31;
    // phase-B / epilogue roles
    const int hoq = tid & 15;
    const int h = (tid >> 4) & 3;
    const int rq = tid >> 6;
    const int ho0 = hoq * 4;

    // e_src tile: flat [r*20 + hh*5 + t]
    for (int idx = tid; idx < RR * HH * TT; idx += 256) {
        const int r = idx / 20, hh = (idx % 20) / 5, t = idx % 5;
        es[idx] = g_es[((b * HH + hh) * TT + t) * NN + i0 + r];
    }

    u64 acc[8][2];
#pragma unroll
    for (int i = 0; i < 8; i++) acc[i][0] = acc[i][1] = 0ull;
    float psum[4][HH];
#pragma unroll
    for (int rl = 0; rl < 4; rl++)
#pragma unroll
        for (int hh = 0; hh < HH; hh++) psum[rl][hh] = 0.f;

    const int* adjp = adj + b * NN * NN + i0 * NN;
    const float* edb = g_ed + b * HH * TT * NN;
    const float* hb = g_h + ((b * HH + h) * NN) * HOO + ho0;

    // ed staging offsets: idx -> (hh = idx/160, t = (idx/32)%5, j = idx%32)
    const int i0e = tid;
    const int i1e = tid + 256;
    const int i2e = tid + 512;   // valid when tid < 128
    const int o0 = (i0e / 160 * 5 + (i0e / 32) % 5) * NN + (i0e & 31);
    const int o1 = (i1e / 160 * 5 + (i1e / 32) % 5) * NN + (i1e & 31);
    const int o2 = (i2e / 160 * 5 + (i2e / 32) % 5) * NN + (i2e & 31);

    float eL0, eL1, eL2 = 0.f;
#define ED_LOAD(j0n)                                              \
    do {                                                          \
        eL0 = __ldg(&edb[o0 + (j0n)]);                            \
        eL1 = __ldg(&edb[o1 + (j0n)]);                            \
        if (tid < 128) eL2 = __ldg(&edb[o2 + (j0n)]);             \
    } while (0)
#define ED_STORE(nb_)                                             \
    do {                                                          \
        ed[(nb_) * 640 + i0e] = eL0;                              \
        ed[(nb_) * 640 + i1e] = eL1;                              \
        if (tid < 128) ed[(nb_) * 640 + i2e] = eL2;               \
    } while (0)

#define PHASE_A(cbuf)                                                          \
    do {                                                                       \
        const float* edc = ed + (cbuf) * 640;                                  \
        u64* psc = ps + (cbuf) * PS_BUF;                                       \
        _Pragma("unroll")                                                      \
        for (int rl = 0; rl < 4; rl++) {                                       \
            const int r = w * 4 + rl;                                          \
            const int t = tcur[rl];                                            \
            _Pragma("unroll")                                                  \
            for (int hh = 0; hh < HH; hh++) {                                  \
                float p = 0.f;                                                 \
                if (t > 0) {                                                   \
                    float s = es[r * 20 + hh * 5 + t - 1] +                    \
                              edc[(hh * 5 + t - 1) * 32 + lane];               \
                    s = s > 0.f ? s : 0.01f * s;                               \
                    p = __expf(s);                                             \
                }                                                              \
                psum[rl][hh] += p;                                             \
                psc[hh * PS_HS + r * 32 + lane] = pack2(p, p);                 \
            }                                                                  \
        }                                                                      \
    } while (0)

#define PHASE_B(jj0, pbuf)                                                     \
    do {                                                                       \
        const u64* psb = ps + (pbuf) * PS_BUF + h * PS_HS + rq * 8 * 32;       \
        _Pragma("unroll")                                                      \
        for (int jg = 0; jg < 8; jg++) {                                       \
            const float* vp = hb + ((jj0) + jg * 4) * HOO;                     \
            const ulonglong2 va = *reinterpret_cast<const ulonglong2*>(vp);    \
            const ulonglong2 vb = *reinterpret_cast<const ulonglong2*>(vp + HOO);      \
            const ulonglong2 vc = *reinterpret_cast<const ulonglong2*>(vp + 2 * HOO);  \
            const ulonglong2 vd = *reinterpret_cast<const ulonglong2*>(vp + 3 * HOO);  \
            _Pragma("unroll")                                                  \
            for (int ri = 0; ri < 8; ri++) {                                   \
                const ulonglong2 pA = *reinterpret_cast<const ulonglong2*>(    \
                    psb + ri * 32 + jg * 4);                                   \
                const ulonglong2 pB = *reinterpret_cast<const ulonglong2*>(    \
                    psb + ri * 32 + jg * 4 + 2);                               \
                fma2(acc[ri][0], pA.x, va.x); fma2(acc[ri][1], pA.x, va.y);    \
                fma2(acc[ri][0], pA.y, vb.x); fma2(acc[ri][1], pA.y, vb.y);    \
                fma2(acc[ri][0], pB.x, vc.x); fma2(acc[ri][1], pB.x, vc.y);    \
                fma2(acc[ri][0], pB.y, vd.x); fma2(acc[ri][1], pB.y, vd.y);    \
            }                                                                  \
        }                                                                      \
    } while (0)

    int tcur[4], tnxt[4];

    // prologue
    ED_LOAD(0);
    ED_STORE(0);
#pragma unroll
    for (int rl = 0; rl < 4; rl++) tcur[rl] = adjp[(w * 4 + rl) * NN + lane];
    __syncthreads();

    for (int c = 0; c < NCH; c++) {
        const int cbuf = c & 1;
        PHASE_A(cbuf);
        if (c + 1 < NCH) {
            const int j0n = (c + 1) * JC;
#pragma unroll
            for (int rl = 0; rl < 4; rl++)
                tnxt[rl] = adjp[(w * 4 + rl) * NN + j0n + lane];
            ED_LOAD(j0n);
        }
        if (c >= 1) PHASE_B((c - 1) * JC, cbuf ^ 1);
        if (c + 1 < NCH) {
            ED_STORE(cbuf ^ 1);
#pragma unroll
            for (int rl = 0; rl < 4; rl++) tcur[rl] = tnxt[rl];
        }
        __syncthreads();
    }
    PHASE_B((NCH - 1) * JC, (NCH - 1) & 1);

    // softmax denominators
#pragma unroll
    for (int rl = 0; rl < 4; rl++)
#pragma unroll
        for (int hh = 0; hh < HH; hh++) {
            float s = psum[rl][hh];
#pragma unroll
            for (int off = 16; off; off >>= 1) s += __shfl_xor_sync(0xffffffffu, s, off);
            if (lane == 0) sums[(w * 4 + rl) * 4 + hh] = s;
        }
    __syncthreads();

    // epilogue: /sum + bias -> relu -> +h -> LN over 64 (16 lanes x 4 ho) -> store
    const float4 bi = *reinterpret_cast<const float4*>(bias + h * HOO + ho0);
    const float4 ga = *reinterpret_cast<const float4*>(gamma + h * HOO + ho0);
    const float4 be = *reinterpret_cast<const float4*>(beta + h * HOO + ho0);

#pragma unroll
    for (int ri = 0; ri < 8; ri++) {
        const int r = rq * 8 + ri;
        const float4 hres = *reinterpret_cast<const float4*>(
            g_h + ((b * HH + h) * NN + i0 + r) * HOO + ho0);
        const float inv = __fdividef(1.f, sums[r * 4 + h]);
        const float2 a0 = unpack2(acc[ri][0]);
        const float2 a1 = unpack2(acc[ri][1]);
        const float v0 = fmaxf(a0.x * inv + bi.x, 0.f) + hres.x;
        const float v1 = fmaxf(a0.y * inv + bi.y, 0.f) + hres.y;
        const float v2 = fmaxf(a1.x * inv + bi.z, 0.f) + hres.z;
        const float v3 = fmaxf(a1.y * inv + bi.w, 0.f) + hres.w;
        float s = v0 + v1 + v2 + v3;
        float s2 = v0 * v0 + v1 * v1 + v2 * v2 + v3 * v3;
#pragma unroll
        for (int off = 8; off; off >>= 1) {
            s += __shfl_xor_sync(0xffffffffu, s, off);
            s2 += __shfl_xor_sync(0xffffffffu, s2, off);
        }
        const float mu = s * (1.f / HOO);
        const float var = s2 * (1.f / HOO) - mu * mu;
        const float rstd = rsqrtf(var + 1e-6f);
        float4 o;
        o.x = (v0 - mu) * rstd * ga.x + be.x;
        o.y = (v1 - mu) * rstd * ga.y + be.y;
        o.z = (v2 - mu) * rstd * ga.z + be.z;
        o.w = (v3 - mu) * rstd * ga.w + be.w;
        *reinterpret_cast<float4*>(out + (b * NN + i0 + r) * (HH * HOO) + h * HOO + ho0) = o;
    }
#undef ED_LOAD
#undef ED_STORE
#undef PHASE_A
#undef PHASE_B
}

// ---------------------------------------------------------------------------
extern "C" void kernel_launch(void* const* d_in, const int* in_sizes, int n_in,
                              void* d_out, int out_size) {
    const float* nodes_embed = (const float*)d_in[0];
    const int*   node_adj    = (const int*)d_in[1];
    const float* W           = (const float*)d_in[2];
    const float* a_src       = (const float*)d_in[3];
    const float* a_dst       = (const float*)d_in[4];
    const float* bias        = (const float*)d_in[5];
    const float* ln_gamma    = (const float*)d_in[6];
    const float* ln_beta     = (const float*)d_in[7];
    float* out = (float*)d_out;

    static bool attr_set = false;
    if (!attr_set) {
        cudaFuncSetAttribute(k_attn, cudaFuncAttributeMaxDynamicSharedMemorySize,
                             K2_SMEM_BYTES);
        attr_set = true;
    }

    k_project<<<BB * NN / 32, 256>>>(nodes_embed, W);
    k_scores<<<BB * NN / 8, 256>>>(a_src, a_dst);
    k_attn<<<dim3(NN / RR, BB), 256, K2_SMEM_BYTES>>>(node_adj, bias, ln_gamma,
                                                      ln_beta, out);
}

// round 10
// speedup vs baseline: 1.2570x; 1.2570x over previous
#include <cuda_runtime.h>

// GraphMultiHeadAttention: B=8, N=1024, D=256, H=4, HO=64, T=5
// K1: h = x @ W (per head), f32x2 packed FMA
// K1b: e_src/e_dst score tables
// K2: masked edge-typed attention + AV (f32x2) + bias/relu/residual/LN + concat
// R7: revert to R2 structure; PHASE_B loads p as u64 pairs (no pack movs).

#define BB 8
#define NN 1024
#define DD 256
#define HH 4
#define HOO 64
#define TT 5
#define RR 32     // rows per CTA in K2
#define JC 32     // j-chunk in K2
#define NCH (NN / JC)

typedef unsigned long long u64;

__device__ float g_h[BB * HH * NN * HOO];      // [B,H,N,HO]
__device__ float g_es[BB * HH * TT * NN];      // [B,H,T,N]
__device__ float g_ed[BB * HH * TT * NN];      // [B,H,T,N]

__device__ __forceinline__ u64 pack2(float lo, float hi) {
    u64 r; asm("mov.b64 %0, {%1, %2};" : "=l"(r) : "f"(lo), "f"(hi)); return r;
}
__device__ __forceinline__ void fma2(u64& acc, u64 a, u64 b) {
    asm("fma.rn.f32x2 %0, %1, %2, %0;" : "+l"(acc) : "l"(a), "l"(b));
}
__device__ __forceinline__ float2 unpack2(u64 v) {
    float2 f; asm("mov.b64 {%0, %1}, %2;" : "=f"(f.x), "=f"(f.y) : "l"(v)); return f;
}

// ---------------------------------------------------------------------------
// K1: projection. Grid: B*N/32 = 256 blocks, 256 threads.
// 32 nodes per CTA; thread owns (h,ho); f32x2 over node pairs.
// ---------------------------------------------------------------------------
__global__ __launch_bounds__(256) void k_project(const float* __restrict__ x,
                                                 const float* __restrict__ W) {
    __shared__ float xs[DD][34];
    const int b = blockIdx.x >> 5;
    const int n0 = (blockIdx.x & 31) * 32;
    const int tid = threadIdx.x;

    {
        const float* xp = x + (b * NN + n0) * DD + tid;
#pragma unroll
        for (int nt = 0; nt < 32; nt++) xs[tid][nt] = xp[nt * DD];
    }
    __syncthreads();

    const int h = tid >> 6, ho = tid & 63;
    u64 acc2[16];
#pragma unroll
    for (int i = 0; i < 16; i++) acc2[i] = 0ull;

    const float* wp = W + h * DD * HOO + ho;
#pragma unroll 4
    for (int d = 0; d < DD; d++) {
        const float w = __ldg(wp + d * HOO);
        const u64 ww = pack2(w, w);
#pragma unroll
        for (int i = 0; i < 16; i++) {
            const u64 xv = *reinterpret_cast<const u64*>(&xs[d][i * 2]);
            fma2(acc2[i], xv, ww);
        }
    }

    float* hp = g_h + ((b * HH + h) * NN + n0) * HOO + ho;
#pragma unroll
    for (int i = 0; i < 16; i++) {
        const float2 f = unpack2(acc2[i]);
        hp[(2 * i + 0) * HOO] = f.x;
        hp[(2 * i + 1) * HOO] = f.y;
    }
}

// ---------------------------------------------------------------------------
// K1b: score tables. Grid: 1024 blocks x 256 threads; warp = one node.
// ---------------------------------------------------------------------------
__global__ __launch_bounds__(256) void k_scores(const float* __restrict__ a_src,
                                                const float* __restrict__ a_dst) {
    const int warp = threadIdx.x >> 5, lane = threadIdx.x & 31;
    const int node = blockIdx.x * 8 + warp;
    const int b = node >> 10;
    const int n = node & (NN - 1);

    float hv[2 * HH];
#pragma unroll
    for (int h = 0; h < HH; h++) {
        const float* hp = g_h + ((b * HH + h) * NN + n) * HOO;
        hv[h * 2 + 0] = hp[lane];
        hv[h * 2 + 1] = hp[32 + lane];
    }

#pragma unroll
    for (int h = 0; h < HH; h++) {
#pragma unroll
        for (int t = 0; t < TT; t++) {
            const int wi = (h * TT + t) * HOO;
            float ps = hv[h * 2] * a_src[wi + lane] + hv[h * 2 + 1] * a_src[wi + 32 + lane];
            float pd = hv[h * 2] * a_dst[wi + lane] + hv[h * 2 + 1] * a_dst[wi + 32 + lane];
#pragma unroll
            for (int off = 16; off; off >>= 1) {
                ps += __shfl_xor_sync(0xffffffffu, ps, off);
                pd += __shfl_xor_sync(0xffffffffu, pd, off);
            }
            if (lane == 0) {
                g_es[(b * HH + h) * TT * NN + t * NN + n] = ps;
                g_ed[(b * HH + h) * TT * NN + t * NN + n] = pd;
            }
        }
    }
}

// ---------------------------------------------------------------------------
// K2: attention + epilogue. Grid: (N/RR=32, B=8), 512 threads, 16 warps.
// Software-pipelined: one __syncthreads per j-chunk; p_s and ed_s double-buffered.
//   phase A (warp = 2 rows, lane = j): p = exp(lrelu(es+ed)) masked; psum in regs
//   phase B (thread = (rhalf,h,ho)): acc2[16 rows] += p * v  via f32x2;
//           p pairs read directly as u64 from smem (no packs in inner loop)
// ---------------------------------------------------------------------------
__global__ __launch_bounds__(512) void k_attn(const int* __restrict__ adj,
                                              const float* __restrict__ bias,
                                              const float* __restrict__ gamma,
                                              const float* __restrict__ beta,
                                              float* __restrict__ out) {
    __shared__ float es_s[RR][HH][TT];                       // 2.5 KB
    __shared__ float ed_s[2][HH * TT * JC];                  // 5 KB
    __shared__ __align__(16) float p_s[2][HH][RR][JC];       // 32 KB
    __shared__ float sum_s[RR][HH];
    __shared__ float2 red_s[RR][HH][2];

    const int b = blockIdx.y;
    const int i0 = blockIdx.x * RR;
    const int tid = threadIdx.x;
    const int w = tid >> 5, lane = tid & 31;
    // phase B / epilogue roles
    const int rh = tid >> 8;                 // 0..1 -> rows [rh*16, rh*16+16)
    const int h = (tid >> 6) & 3;
    const int ho = tid & 63;
    const int r0 = rh * 16;
    const int half = (tid >> 5) & 1;

    // e_src tile for our 32 rows
    for (int idx = tid; idx < RR * HH * TT; idx += 512) {
        const int r = idx / (HH * TT);
        const int rem = idx % (HH * TT);
        es_s[r][rem / TT][rem % TT] =
            g_es[(b * HH + rem / TT) * TT * NN + (rem % TT) * NN + i0 + r];
    }

    u64 acc2[16];
#pragma unroll
    for (int i = 0; i < 16; i++) acc2[i] = 0ull;
    float psum[2][HH];
#pragma unroll
    for (int rl = 0; rl < 2; rl++)
#pragma unroll
        for (int hh = 0; hh < HH; hh++) psum[rl][hh] = 0.f;

    const int* adjp = adj + b * NN * NN + i0 * NN;
    const float* edb = g_ed + b * HH * TT * NN;
    const float* hb = g_h + ((b * HH + h) * NN) * HOO + ho;

    // ed-chunk staging map: idx -> (hh, t, j); global off = (hh*TT+t)*NN + j0 + j
    const int s_off = ((tid / (TT * JC)) * TT + (tid % (TT * JC)) / JC) * NN + (tid & (JC - 1));
    const int tid2 = tid + 512;                            // 512..639 (tid<128)
    const int s2_off = ((tid2 / (TT * JC)) * TT + (tid2 % (TT * JC)) / JC) * NN + (tid2 & (JC - 1));

#define STAGE_ED_LOAD(j0next)                                   \
    do {                                                        \
        e0 = __ldg(&edb[s_off + (j0next)]);                     \
        if (tid < 128) e1 = __ldg(&edb[s2_off + (j0next)]);     \
    } while (0)

#define STAGE_ED_STORE(nb)                                      \
    do {                                                        \
        ed_s[nb][tid] = e0;                                     \
        if (tid < 128) ed_s[nb][tid2] = e1;                     \
    } while (0)

#define PHASE_A(cbuf, jj0)                                                     \
    do {                                                                       \
        const float* edc = ed_s[cbuf];                                         \
        _Pragma("unroll")                                                      \
        for (int rl = 0; rl < 2; rl++) {                                       \
            const int r = w * 2 + rl;                                          \
            const int t = (rl == 0) ? t0 : t1;                                 \
            _Pragma("unroll")                                                  \
            for (int hh = 0; hh < HH; hh++) {                                  \
                float p = 0.f;                                                 \
                if (t > 0) {                                                   \
                    float s = es_s[r][hh][t - 1] +                             \
                              edc[(hh * TT + (t - 1)) * JC + lane];            \
                    s = s > 0.f ? s : 0.01f * s;                               \
                    p = __expf(s);                                             \
                }                                                              \
                psum[rl][hh] += p;                                             \
                p_s[cbuf][hh][r][lane] = p;                                    \
            }                                                                  \
        }                                                                      \
    } while (0)

#define PHASE_B(jj0, pbuf)                                                     \
    do {                                                                       \
        _Pragma("unroll")                                                      \
        for (int jg = 0; jg < JC / 4; jg++) {                                  \
            const float* vp = hb + ((jj0) + jg * 4) * HOO;                     \
            const float v0 = __ldg(vp);                                        \
            const float v1 = __ldg(vp + HOO);                                  \
            const float v2 = __ldg(vp + 2 * HOO);                              \
            const float v3 = __ldg(vp + 3 * HOO);                              \
            const u64 v01 = pack2(v0, v1);                                     \
            const u64 v23 = pack2(v2, v3);                                     \
            _Pragma("unroll")                                                  \
            for (int ri = 0; ri < 16; ri++) {                                  \
                const ulonglong2 pv = *reinterpret_cast<const ulonglong2*>(    \
                    &p_s[pbuf][h][r0 + ri][jg * 4]);                           \
                fma2(acc2[ri], pv.x, v01);                                     \
                fma2(acc2[ri], pv.y, v23);                                     \
            }                                                                  \
        }                                                                      \
    } while (0)

    float e0 = 0.f, e1 = 0.f;
    int t0, t1;

    // ---- pipeline prologue ----
    STAGE_ED_LOAD(0);
    STAGE_ED_STORE(0);
    __syncthreads();
    t0 = adjp[(w * 2 + 0) * NN + lane];
    t1 = adjp[(w * 2 + 1) * NN + lane];
    STAGE_ED_LOAD(JC);                 // chunk 1 loads in flight
    PHASE_A(0, 0);
    STAGE_ED_STORE(1);
    __syncthreads();

    // ---- main pipeline: one sync per chunk ----
    for (int c = 1; c < NCH; c++) {
        const int j0 = c * JC;
        const int cbuf = c & 1;
        t0 = adjp[(w * 2 + 0) * NN + j0 + lane];
        t1 = adjp[(w * 2 + 1) * NN + j0 + lane];
        if (c + 1 < NCH) STAGE_ED_LOAD(j0 + JC);
        PHASE_B(j0 - JC, cbuf ^ 1);
        PHASE_A(cbuf, j0);
        if (c + 1 < NCH) STAGE_ED_STORE(cbuf ^ 1);
        __syncthreads();
    }
    PHASE_B(NN - JC, (NCH - 1) & 1);

    // ---- softmax denominators ----
#pragma unroll
    for (int rl = 0; rl < 2; rl++)
#pragma unroll
        for (int hh = 0; hh < HH; hh++) {
            float s = psum[rl][hh];
#pragma unroll
            for (int off = 16; off; off >>= 1) s += __shfl_xor_sync(0xffffffffu, s, off);
            if (lane == 0) sum_s[w * 2 + rl][hh] = s;
        }
    __syncthreads();

    // ---- epilogue: /sum + bias -> relu -> +h -> LayerNorm -> concat store ----
    const float bias_v = bias[h * HOO + ho];
    const float gam = gamma[h * HOO + ho];
    const float bet = beta[h * HOO + ho];

#pragma unroll
    for (int ri = 0; ri < 16; ri++) {
        const int r = r0 + ri;
        const float2 f = unpack2(acc2[ri]);
        const float hres = hb[(i0 + r) * HOO];
        float v = __fdividef(f.x + f.y, sum_s[r][h]) + bias_v;
        v = fmaxf(v, 0.f) + hres;
        acc2[ri] = pack2(v, v);
        float s = v, s2 = v * v;
#pragma unroll
        for (int off = 16; off; off >>= 1) {
            s += __shfl_xor_sync(0xffffffffu, s, off);
            s2 += __shfl_xor_sync(0xffffffffu, s2, off);
        }
        if (lane == 0) red_s[r][h][half] = make_float2(s, s2);
    }
    __syncthreads();

#pragma unroll
    for (int ri = 0; ri < 16; ri++) {
        const int r = r0 + ri;
        const float2 a0 = red_s[r][h][0];
        const float2 a1 = red_s[r][h][1];
        const float mu = (a0.x + a1.x) * (1.f / HOO);
        const float var = (a0.y + a1.y) * (1.f / HOO) - mu * mu;
        const float o = (unpack2(acc2[ri]).x - mu) * rsqrtf(var + 1e-6f) * gam + bet;
        out[(b * NN + i0 + r) * (HH * HOO) + h * HOO + ho] = o;
    }
#undef STAGE_ED_LOAD
#undef STAGE_ED_STORE
#undef PHASE_A
#undef PHASE_B
}

// ---------------------------------------------------------------------------
extern "C" void kernel_launch(void* const* d_in, const int* in_sizes, int n_in,
                              void* d_out, int out_size) {
    const float* nodes_embed = (const float*)d_in[0];
    const int*   node_adj    = (const int*)d_in[1];
    const float* W           = (const float*)d_in[2];
    const float* a_src       = (const float*)d_in[3];
    const float* a_dst       = (const float*)d_in[4];
    const float* bias        = (const float*)d_in[5];
    const float* ln_gamma    = (const float*)d_in[6];
    const float* ln_beta     = (const float*)d_in[7];
    float* out = (float*)d_out;

    k_project<<<BB * NN / 32, 256>>>(nodes_embed, W);
    k_scores<<<BB * NN / 8, 256>>>(a_src, a_dst);
    k_attn<<<dim3(NN / RR, BB), 512>>>(node_adj, bias, ln_gamma, ln_beta, out);
}